// round 11
// baseline (speedup 1.0000x reference)
#include <cuda_runtime.h>
#include <cstdint>

typedef unsigned long long ull;

// ---- packed f32x2 helpers: per-lane IEEE fp32 semantics ----
__device__ __forceinline__ ull fma2(ull a, ull b, ull c) {
    ull d;
    asm("fma.rn.f32x2 %0, %1, %2, %3;" : "=l"(d) : "l"(a), "l"(b), "l"(c));
    return d;
}
__device__ __forceinline__ ull add2(ull a, ull b) {
    ull d;
    asm("add.rn.f32x2 %0, %1, %2;" : "=l"(d) : "l"(a), "l"(b));
    return d;
}
__device__ __forceinline__ float ulo(ull v) { return __uint_as_float((unsigned)v); }
__device__ __forceinline__ float uhi(ull v) { return __uint_as_float((unsigned)(v >> 32)); }
__device__ __forceinline__ ull dup2(float x) {
    unsigned u = __float_as_uint(x);
    return ((ull)u << 32) | (ull)u;
}

static constexpr int D       = 64;
static constexpr int HW      = 4096;
static constexpr int K       = 512;
static constexpr int N_VEC   = 131072;
static constexpr int N_ELEMS = N_VEC * D;         // 8388608
static constexpr int LOSS_OFF = N_ELEMS;
static constexpr int IDX_OFF  = N_ELEMS + 1;
static constexpr int THREADS  = 512;
static constexpr int NCTA     = 148;
static constexpr int VTILE    = 128;              // vectors per CTA-tile
static constexpr int NTILE    = N_VEC / VTILE;    // 1024

// smem layout (floats)
static constexpr int OFF_T  = 0;                  // sT  [64][512] codebook transposed
static constexpr int OFF_E  = 32768;              // sE  [512]
static constexpr int OFF_X2 = 33280;              // sX2 [64][128] ull, x pre-duplicated (16384 floats)
static constexpr int OFF_S  = 49664;              // sS  [128]
static constexpr int OFF_B  = 49792;              // sB  [128]
static constexpr int OFF_CD = 49920;              // sCd [128][16]
static constexpr int OFF_CI = 51968;              // sCi [128][16]
static constexpr int SMEM_FLOATS = 54016;
static constexpr int SMEM_BYTES  = SMEM_FLOATS * 4;   // 216064

__device__ double   g_loss = 0.0;
__device__ unsigned g_done = 0u;

// Persistent: 148 CTAs x 512 threads; CTA tile = 128 vec x 512 codes (R9 structure).
// x stored PRE-DUPLICATED as (x,x) ull in smem -> mainloop has ZERO dup-movs:
// per d-iter: 2 x-LDS.128 (dense) + 4 e-LDS.128 (broadcast) + 32 fma2, linear immediate
// addressing (no clamped prefetch indices).
// EXACT-INVARIANT (verified rel_err==0.0 seven times, do not change):
//   d_k  = fl32( fl32(S + E_k) + (-2)*dot_k )
//   dot_k = strict sequential fp32 FMA chain over d=0..63
//   S     = 4-lane stride-4 sums combined (l0+l2)+(l1+l3)
//   argmin: strict '<', first-min ascending k (lane0<lane1; asc c; asc pass; asc tk)
//   out   = fl(x + fl(q - x))
__global__ __launch_bounds__(THREADS, 1)
void k_main(const float* __restrict__ in, const float* __restrict__ emb,
            float* __restrict__ out, int write_extras) {
    extern __shared__ float s[];
    float* sT  = s + OFF_T;
    float* sE  = s + OFF_E;
    ull*   sX2 = (ull*)(s + OFF_X2);          // [64][128] duplicated x
    const float* sXf = (const float*)(s + OFF_X2);  // low-word view: x at 2*(d*128+v)
    float* sS  = s + OFF_S;
    int*   sB  = (int*)(s + OFF_B);
    float* sCd = s + OFF_CD;
    int*   sCi = (int*)(s + OFF_CI);
    __shared__ double red[16];

    const int tid = threadIdx.x;
    const int tv  = tid & 31;    // 4 vecs [tv*4, tv*4+3]
    const int tk  = tid >> 5;    // 32 codes [tk*32, tk*32+31]

    // ---- stage codebook TRANSPOSED ----
#pragma unroll
    for (int i = 0; i < 64; i++) {
        int lin = i * THREADS + tid;
        int k = lin & 511;
        int d = lin >> 9;
        sT[d * K + k] = emb[k * D + d];
    }

    // ---- E_k: XLA 4-lane pattern, 1 code/thread ----
    {
        const float* r = emb + tid * D;
        float l0 = 0.f, l1 = 0.f, l2 = 0.f, l3 = 0.f;
#pragma unroll
        for (int i = 0; i < 16; i++) {
            l0 = __fadd_rn(l0, __fmul_rn(r[4 * i + 0], r[4 * i + 0]));
            l1 = __fadd_rn(l1, __fmul_rn(r[4 * i + 1], r[4 * i + 1]));
            l2 = __fadd_rn(l2, __fmul_rn(r[4 * i + 2], r[4 * i + 2]));
            l3 = __fadd_rn(l3, __fmul_rn(r[4 * i + 3], r[4 * i + 3]));
        }
        sE[tid] = __fadd_rn(__fadd_rn(l0, l2), __fadd_rn(l1, l3));
    }
    __syncthreads();

    const ull NEG2 = dup2(-2.0f);
    float lsumf = 0.0f;

    for (int tile = blockIdx.x; tile < NTILE; tile += NCTA) {
        const int v0 = tile * VTILE;
        const int b  = v0 >> 12;
        const int p  = v0 & 4095;
        const float* xg = in + b * (D * HW) + p;

        // ---- stage x tile, PRE-DUPLICATED (coalesced LDG, STS.64) ----
#pragma unroll
        for (int i = 0; i < 16; i++) {
            int lin = i * THREADS + tid;       // 0..8191
            int d   = lin >> 7;
            int vv2 = lin & 127;
            sX2[lin] = dup2(xg[d * HW + vv2]);
        }
        __syncthreads();

        // ---- S per vector (threads 0..127), exact 4-lane pattern ----
        if (tid < VTILE) {
            float l0 = 0.f, l1 = 0.f, l2 = 0.f, l3 = 0.f;
#pragma unroll
            for (int d = 0; d < 64; d += 4) {
                float x0 = sXf[2 * ((d + 0) * VTILE + tid)];
                float x1 = sXf[2 * ((d + 1) * VTILE + tid)];
                float x2 = sXf[2 * ((d + 2) * VTILE + tid)];
                float x3 = sXf[2 * ((d + 3) * VTILE + tid)];
                l0 = __fadd_rn(l0, __fmul_rn(x0, x0));
                l1 = __fadd_rn(l1, __fmul_rn(x1, x1));
                l2 = __fadd_rn(l2, __fmul_rn(x2, x2));
                l3 = __fadd_rn(l3, __fmul_rn(x3, x3));
            }
            sS[tid] = __fadd_rn(__fadd_rn(l0, l2), __fadd_rn(l1, l3));
        }
        __syncthreads();

        // ---- per-vec running best across both k-passes ----
        float bestD[4];
        int   bestI[4];
#pragma unroll
        for (int vp = 0; vp < 4; vp++) { bestD[vp] = 3.4e38f; bestI[vp] = 0; }

        const float4 Sv = *(const float4*)(sS + tv * 4);
        const ull Sd[4] = { dup2(Sv.x), dup2(Sv.y), dup2(Sv.z), dup2(Sv.w) };

        for (int pass = 0; pass < 2; pass++) {
            const int kb = tk * 32 + pass * 16;
            ull acc[32];
#pragma unroll
            for (int i = 0; i < 32; i++) acc[i] = 0ull;

            const ull*   xp = sX2 + tv * 4;
            const float* ep = sT + kb;

#pragma unroll 4
            for (int d = 0; d < 64; d++) {
                // dense LDS.128 x2: duplicated x pairs, no movs
                ulonglong2 x01 = *(const ulonglong2*)(xp + d * VTILE);
                ulonglong2 x23 = *(const ulonglong2*)(xp + d * VTILE + 2);
                // broadcast LDS.128 x4: 8 code-pairs
                const ulonglong2* eq = (const ulonglong2*)(ep + d * K);
                ulonglong2 e01 = eq[0], e23 = eq[1], e45 = eq[2], e67 = eq[3];
                ull ev[8] = { e01.x, e01.y, e23.x, e23.y, e45.x, e45.y, e67.x, e67.y };
#pragma unroll
                for (int c = 0; c < 8; c++) {
                    acc[0 * 8 + c] = fma2(x01.x, ev[c], acc[0 * 8 + c]);
                    acc[1 * 8 + c] = fma2(x01.y, ev[c], acc[1 * 8 + c]);
                    acc[2 * 8 + c] = fma2(x23.x, ev[c], acc[2 * 8 + c]);
                    acc[3 * 8 + c] = fma2(x23.y, ev[c], acc[3 * 8 + c]);
                }
            }

            // epilogue: distances + running argmin (ascending k)
            const ull* epE = (const ull*)(sE + kb);
#pragma unroll
            for (int c = 0; c < 8; c++) {
                ull Ec = epE[c];
                const int k0 = kb + 2 * c;
#pragma unroll
                for (int vp = 0; vp < 4; vp++) {
                    ull t1 = add2(Sd[vp], Ec);                 // fl(S + E)
                    ull dd = fma2(acc[vp * 8 + c], NEG2, t1);  // fl(t1 - 2*dot)
                    float d0 = ulo(dd), d1 = uhi(dd);
                    if (d0 < bestD[vp]) { bestD[vp] = d0; bestI[vp] = k0; }
                    if (d1 < bestD[vp]) { bestD[vp] = d1; bestI[vp] = k0 + 1; }
                }
            }
        }

        // ---- publish candidates [vec][tk] ----
#pragma unroll
        for (int vp = 0; vp < 4; vp++) {
            const int vvp = tv * 4 + vp;
            sCd[vvp * 16 + tk] = bestD[vp];
            sCi[vvp * 16 + tk] = bestI[vp];
        }
        __syncthreads();

        // ---- final reduce per vec (ascending tk = ascending k) ----
        if (tid < VTILE) {
            float best = 3.4e38f;
            int bi = 0;
#pragma unroll
            for (int t2 = 0; t2 < 16; t2++) {
                float dd = sCd[tid * 16 + t2];
                if (dd < best) { best = dd; bi = sCi[tid * 16 + t2]; }
            }
            sB[tid] = bi;
            if (write_extras) out[IDX_OFF + v0 + tid] = (float)bi;
        }
        __syncthreads();

        // ---- gather + straight-through store + loss (fp32): 16 elems/thread ----
        {
            const int vv2 = tid & 127;
            const int d0  = (tid >> 7) * 16;
            const int bi  = sB[vv2];
            float* og = out + b * (D * HW) + p + vv2;
#pragma unroll
            for (int j = 0; j < 16; j++) {
                const int d = d0 + j;
                float q  = sT[d * K + bi];
                float xs = sXf[2 * (d * VTILE + vv2)];
                float t  = __fsub_rn(q, xs);       // fl(q - x)
                og[d * HW] = __fadd_rn(xs, t);     // fl(x + (q - x))
                lsumf = __fmaf_rn(t, t, lsumf);
            }
        }
        __syncthreads();   // protect sX2/sCd/sB before next tile
    }

    // ---- loss block-reduce (fp32 shfl, double combine) -> one atomic/CTA ----
#pragma unroll
    for (int o = 16; o; o >>= 1) lsumf += __shfl_down_sync(0xffffffffu, lsumf, o);
    if ((tid & 31) == 0) red[tid >> 5] = (double)lsumf;
    __syncthreads();
    if (tid == 0) {
        double t = 0.0;
#pragma unroll
        for (int w = 0; w < 16; w++) t += red[w];
        atomicAdd(&g_loss, t);
        __threadfence();
        unsigned done = atomicAdd(&g_done, 1u);
        if (done == (unsigned)(gridDim.x - 1)) {
            if (write_extras)
                out[LOSS_OFF] = (float)(0.25 * g_loss / (double)N_ELEMS);
            g_loss = 0.0;
            g_done = 0u;
        }
    }
}

extern "C" void kernel_launch(void* const* d_in, const int* in_sizes, int n_in,
                              void* d_out, int out_size) {
    const float* in  = (const float*)d_in[0];
    const float* emb = (const float*)d_in[1];
    if (n_in >= 2 && in_sizes[0] == K * D && in_sizes[1] == N_ELEMS) {
        const float* t = in; in = emb; emb = t;
    }
    float* out = (float*)d_out;

    cudaFuncSetAttribute(k_main, cudaFuncAttributeMaxDynamicSharedMemorySize, SMEM_BYTES);

    const int extras = (out_size > N_ELEMS) ? 1 : 0;

    k_main<<<NCTA, THREADS, SMEM_BYTES>>>(in, emb, out, extras);
}

// round 12
// speedup vs baseline: 1.1204x; 1.1204x over previous
#include <cuda_runtime.h>
#include <cstdint>

typedef unsigned long long ull;

// ---- packed f32x2 helpers: per-lane IEEE fp32 semantics ----
__device__ __forceinline__ ull fma2(ull a, ull b, ull c) {
    ull d;
    asm("fma.rn.f32x2 %0, %1, %2, %3;" : "=l"(d) : "l"(a), "l"(b), "l"(c));
    return d;
}
__device__ __forceinline__ ull add2(ull a, ull b) {
    ull d;
    asm("add.rn.f32x2 %0, %1, %2;" : "=l"(d) : "l"(a), "l"(b));
    return d;
}
__device__ __forceinline__ float ulo(ull v) { return __uint_as_float((unsigned)v); }
__device__ __forceinline__ float uhi(ull v) { return __uint_as_float((unsigned)(v >> 32)); }
__device__ __forceinline__ ull dup2a(float x) {
    ull d;
    asm("mov.b64 %0, {%1, %1};" : "=l"(d) : "f"(x));
    return d;
}
__device__ __forceinline__ ull dup2(float x) {
    unsigned u = __float_as_uint(x);
    return ((ull)u << 32) | (ull)u;
}
__device__ __forceinline__ void cpasync4(unsigned dst, const float* src) {
    asm volatile("cp.async.ca.shared.global [%0], [%1], 4;" :: "r"(dst), "l"(src));
}

static constexpr int D       = 64;
static constexpr int HW      = 4096;
static constexpr int K       = 512;
static constexpr int N_VEC   = 131072;
static constexpr int N_ELEMS = N_VEC * D;         // 8388608
static constexpr int LOSS_OFF = N_ELEMS;
static constexpr int IDX_OFF  = N_ELEMS + 1;
static constexpr int THREADS  = 512;
static constexpr int NCTA     = 148;
static constexpr int VTILE    = 128;              // vectors per CTA-tile
static constexpr int NTILE    = N_VEC / VTILE;    // 1024

// smem layout (floats)
static constexpr int OFF_T  = 0;                  // sT  [64][512]
static constexpr int OFF_E  = 32768;              // sE  [512]
static constexpr int OFF_X  = 33280;              // sX  [2][64][128] double-buffered
static constexpr int OFF_S  = 49664;              // sS  [128]
static constexpr int OFF_B  = 49792;              // sB  [128]
static constexpr int OFF_CD = 49920;              // sCd [128][16]
static constexpr int OFF_CI = 51968;              // sCi [128][16]
static constexpr int SMEM_FLOATS = 54016;
static constexpr int SMEM_BYTES  = SMEM_FLOATS * 4;   // 216064

__device__ double   g_loss = 0.0;
__device__ unsigned g_done = 0u;

// R9 structure (best: 207.6us, fma 53.5%) + cp.async double-buffered staging:
// next tile's x streams into the alternate buffer DURING the mainloop (LDGSTS,
// no regs, no STS), wait_group at tile end. Everything else identical to R9.
// EXACT-INVARIANT (verified rel_err==0.0 eight times, do not change):
//   d_k  = fl32( fl32(S + E_k) + (-2)*dot_k )
//   dot_k = strict sequential fp32 FMA chain over d=0..63
//   S     = 4-lane stride-4 sums combined (l0+l2)+(l1+l3)
//   argmin: strict '<', first-min ascending k (lane0<lane1; asc c; asc pass; asc tk)
//   out   = fl(x + fl(q - x))
__global__ __launch_bounds__(THREADS, 1)
void k_main(const float* __restrict__ in, const float* __restrict__ emb,
            float* __restrict__ out, int write_extras) {
    extern __shared__ float s[];
    float* sT  = s + OFF_T;
    float* sE  = s + OFF_E;
    float* sX  = s + OFF_X;    // [2][8192]
    float* sS  = s + OFF_S;
    int*   sB  = (int*)(s + OFF_B);
    float* sCd = s + OFF_CD;
    int*   sCi = (int*)(s + OFF_CI);
    __shared__ double red[16];

    const int tid = threadIdx.x;
    const int tv  = tid & 31;    // 4 vecs [tv*4, tv*4+3]
    const int tk  = tid >> 5;    // 32 codes [tk*32, tk*32+31]
    const unsigned sx_u32 = (unsigned)__cvta_generic_to_shared(sX);

    // ---- stage codebook TRANSPOSED ----
#pragma unroll
    for (int i = 0; i < 64; i++) {
        int lin = i * THREADS + tid;
        int k = lin & 511;
        int d = lin >> 9;
        sT[d * K + k] = emb[k * D + d];
    }

    // ---- E_k: XLA 4-lane pattern, 1 code/thread ----
    {
        const float* r = emb + tid * D;
        float l0 = 0.f, l1 = 0.f, l2 = 0.f, l3 = 0.f;
#pragma unroll
        for (int i = 0; i < 16; i++) {
            l0 = __fadd_rn(l0, __fmul_rn(r[4 * i + 0], r[4 * i + 0]));
            l1 = __fadd_rn(l1, __fmul_rn(r[4 * i + 1], r[4 * i + 1]));
            l2 = __fadd_rn(l2, __fmul_rn(r[4 * i + 2], r[4 * i + 2]));
            l3 = __fadd_rn(l3, __fmul_rn(r[4 * i + 3], r[4 * i + 3]));
        }
        sE[tid] = __fadd_rn(__fadd_rn(l0, l2), __fadd_rn(l1, l3));
    }

    const ull NEG2 = dup2(-2.0f);
    float lsumf = 0.0f;
    int bf = 0;

    // ---- prologue: cp.async first tile into buffer 0 ----
    {
        const int v0 = blockIdx.x * VTILE;
        const float* xg = in + (v0 >> 12) * (D * HW) + (v0 & 4095);
#pragma unroll
        for (int i = 0; i < 16; i++) {
            int lin = i * THREADS + tid;
            int d = lin >> 7, vv2 = lin & 127;
            cpasync4(sx_u32 + lin * 4, xg + d * HW + vv2);
        }
        asm volatile("cp.async.commit_group;");
        asm volatile("cp.async.wait_group 0;");
    }
    __syncthreads();

    for (int tile = blockIdx.x; tile < NTILE; tile += NCTA, bf ^= 1) {
        const int v0 = tile * VTILE;
        const int b  = v0 >> 12;
        const int p  = v0 & 4095;
        float* sXb = sX + bf * 8192;

        // ---- issue cp.async prefetch of NEXT tile into alternate buffer ----
        const int nt = tile + NCTA;
        if (nt < NTILE) {
            const int nv0 = nt * VTILE;
            const float* xg2 = in + (nv0 >> 12) * (D * HW) + (nv0 & 4095);
            const unsigned dstb = sx_u32 + ((bf ^ 1) * 8192) * 4;
#pragma unroll
            for (int i = 0; i < 16; i++) {
                int lin = i * THREADS + tid;
                int d = lin >> 7, vv2 = lin & 127;
                cpasync4(dstb + lin * 4, xg2 + d * HW + vv2);
            }
            asm volatile("cp.async.commit_group;");
        }

        // ---- S per vector (threads 0..127), exact 4-lane pattern ----
        if (tid < VTILE) {
            float l0 = 0.f, l1 = 0.f, l2 = 0.f, l3 = 0.f;
#pragma unroll
            for (int d = 0; d < 64; d += 4) {
                float x0 = sXb[(d + 0) * VTILE + tid];
                float x1 = sXb[(d + 1) * VTILE + tid];
                float x2 = sXb[(d + 2) * VTILE + tid];
                float x3 = sXb[(d + 3) * VTILE + tid];
                l0 = __fadd_rn(l0, __fmul_rn(x0, x0));
                l1 = __fadd_rn(l1, __fmul_rn(x1, x1));
                l2 = __fadd_rn(l2, __fmul_rn(x2, x2));
                l3 = __fadd_rn(l3, __fmul_rn(x3, x3));
            }
            sS[tid] = __fadd_rn(__fadd_rn(l0, l2), __fadd_rn(l1, l3));
        }
        __syncthreads();

        // ---- per-vec running best across both k-passes ----
        float bestD[4];
        int   bestI[4];
#pragma unroll
        for (int vp = 0; vp < 4; vp++) { bestD[vp] = 3.4e38f; bestI[vp] = 0; }

        const float4 Sv = *(const float4*)(sS + tv * 4);
        const ull Sd[4] = { dup2(Sv.x), dup2(Sv.y), dup2(Sv.z), dup2(Sv.w) };

        for (int pass = 0; pass < 2; pass++) {
            const int kb = tk * 32 + pass * 16;
            ull acc[32];
#pragma unroll
            for (int i = 0; i < 32; i++) acc[i] = 0ull;

            const float* xp = sXb + tv * 4;
            const float* ep = sT + kb;

            // depth-1 software pipeline (clamped next-index keeps loads in-bounds)
            float4 xv = *(const float4*)(xp);
            ulonglong2 E0 = ((const ulonglong2*)ep)[0];
            ulonglong2 E1 = ((const ulonglong2*)ep)[1];
            ulonglong2 E2 = ((const ulonglong2*)ep)[2];
            ulonglong2 E3 = ((const ulonglong2*)ep)[3];

#pragma unroll 2
            for (int d = 0; d < 64; d++) {
                const int dn = (d < 63) ? d + 1 : 63;
                const float* xq = xp + dn * VTILE;
                const ulonglong2* eq = (const ulonglong2*)(ep + dn * K);
                float4 xn = *(const float4*)(xq);
                ulonglong2 N0 = eq[0], N1 = eq[1], N2 = eq[2], N3 = eq[3];

                ull x0 = dup2a(xv.x);
                ull x1 = dup2a(xv.y);
                ull x2 = dup2a(xv.z);
                ull x3 = dup2a(xv.w);
                ull ev[8] = { E0.x, E0.y, E1.x, E1.y, E2.x, E2.y, E3.x, E3.y };
#pragma unroll
                for (int c = 0; c < 8; c++) {
                    acc[0 * 8 + c] = fma2(x0, ev[c], acc[0 * 8 + c]);
                    acc[1 * 8 + c] = fma2(x1, ev[c], acc[1 * 8 + c]);
                    acc[2 * 8 + c] = fma2(x2, ev[c], acc[2 * 8 + c]);
                    acc[3 * 8 + c] = fma2(x3, ev[c], acc[3 * 8 + c]);
                }
                xv = xn; E0 = N0; E1 = N1; E2 = N2; E3 = N3;
            }

            // epilogue: distances + running argmin (ascending k)
            const ull* epE = (const ull*)(sE + kb);
#pragma unroll
            for (int c = 0; c < 8; c++) {
                ull Ec = epE[c];
                const int k0 = kb + 2 * c;
#pragma unroll
                for (int vp = 0; vp < 4; vp++) {
                    ull t1 = add2(Sd[vp], Ec);                 // fl(S + E)
                    ull dd = fma2(acc[vp * 8 + c], NEG2, t1);  // fl(t1 - 2*dot)
                    float d0 = ulo(dd), d1 = uhi(dd);
                    if (d0 < bestD[vp]) { bestD[vp] = d0; bestI[vp] = k0; }
                    if (d1 < bestD[vp]) { bestD[vp] = d1; bestI[vp] = k0 + 1; }
                }
            }
        }

        // ---- publish candidates [vec][tk] ----
#pragma unroll
        for (int vp = 0; vp < 4; vp++) {
            const int vvp = tv * 4 + vp;
            sCd[vvp * 16 + tk] = bestD[vp];
            sCi[vvp * 16 + tk] = bestI[vp];
        }
        __syncthreads();

        // ---- final reduce per vec (ascending tk = ascending k) ----
        if (tid < VTILE) {
            float best = 3.4e38f;
            int bi = 0;
#pragma unroll
            for (int t2 = 0; t2 < 16; t2++) {
                float dd = sCd[tid * 16 + t2];
                if (dd < best) { best = dd; bi = sCi[tid * 16 + t2]; }
            }
            sB[tid] = bi;
            if (write_extras) out[IDX_OFF + v0 + tid] = (float)bi;
        }
        __syncthreads();

        // ---- gather + straight-through store + loss (fp32): 16 elems/thread ----
        {
            const int vv2 = tid & 127;
            const int d0  = (tid >> 7) * 16;
            const int bi  = sB[vv2];
            float* og = out + b * (D * HW) + p + vv2;
#pragma unroll
            for (int j = 0; j < 16; j++) {
                const int d = d0 + j;
                float q  = sT[d * K + bi];
                float xs = sXb[d * VTILE + vv2];
                float t  = __fsub_rn(q, xs);       // fl(q - x)
                og[d * HW] = __fadd_rn(xs, t);     // fl(x + (q - x))
                lsumf = __fmaf_rn(t, t, lsumf);
            }
        }

        // ---- next tile's cp.async must be complete + visible CTA-wide ----
        asm volatile("cp.async.wait_group 0;");
        __syncthreads();
    }

    // ---- loss block-reduce (fp32 shfl, double combine) -> one atomic/CTA ----
#pragma unroll
    for (int o = 16; o; o >>= 1) lsumf += __shfl_down_sync(0xffffffffu, lsumf, o);
    if ((tid & 31) == 0) red[tid >> 5] = (double)lsumf;
    __syncthreads();
    if (tid == 0) {
        double t = 0.0;
#pragma unroll
        for (int w = 0; w < 16; w++) t += red[w];
        atomicAdd(&g_loss, t);
        __threadfence();
        unsigned done = atomicAdd(&g_done, 1u);
        if (done == (unsigned)(gridDim.x - 1)) {
            if (write_extras)
                out[LOSS_OFF] = (float)(0.25 * g_loss / (double)N_ELEMS);
            g_loss = 0.0;
            g_done = 0u;
        }
    }
}

extern "C" void kernel_launch(void* const* d_in, const int* in_sizes, int n_in,
                              void* d_out, int out_size) {
    const float* in  = (const float*)d_in[0];
    const float* emb = (const float*)d_in[1];
    if (n_in >= 2 && in_sizes[0] == K * D && in_sizes[1] == N_ELEMS) {
        const float* t = in; in = emb; emb = t;
    }
    float* out = (float*)d_out;

    cudaFuncSetAttribute(k_main, cudaFuncAttributeMaxDynamicSharedMemorySize, SMEM_BYTES);

    const int extras = (out_size > N_ELEMS) ? 1 : 0;

    k_main<<<NCTA, THREADS, SMEM_BYTES>>>(in, emb, out, extras);
}

// round 13
// speedup vs baseline: 1.2683x; 1.1320x over previous
#include <cuda_runtime.h>
#include <cstdint>

typedef unsigned long long ull;

// ---- packed f32x2 helpers: per-lane IEEE fp32 semantics ----
__device__ __forceinline__ ull fma2(ull a, ull b, ull c) {
    ull d;
    asm("fma.rn.f32x2 %0, %1, %2, %3;" : "=l"(d) : "l"(a), "l"(b), "l"(c));
    return d;
}
__device__ __forceinline__ ull add2(ull a, ull b) {
    ull d;
    asm("add.rn.f32x2 %0, %1, %2;" : "=l"(d) : "l"(a), "l"(b));
    return d;
}
__device__ __forceinline__ float ulo(ull v) { return __uint_as_float((unsigned)v); }
__device__ __forceinline__ float uhi(ull v) { return __uint_as_float((unsigned)(v >> 32)); }
__device__ __forceinline__ ull dup2a(float x) {
    ull d;
    asm("mov.b64 %0, {%1, %1};" : "=l"(d) : "f"(x));
    return d;
}
__device__ __forceinline__ ull dup2(float x) {
    unsigned u = __float_as_uint(x);
    return ((ull)u << 32) | (ull)u;
}

static constexpr int D       = 64;
static constexpr int HW      = 4096;
static constexpr int K       = 512;
static constexpr int N_VEC   = 131072;
static constexpr int N_ELEMS = N_VEC * D;         // 8388608
static constexpr int LOSS_OFF = N_ELEMS;
static constexpr int IDX_OFF  = N_ELEMS + 1;
static constexpr int THREADS  = 512;
static constexpr int NCTA     = 148;
static constexpr int VTILE    = 128;              // vectors per CTA-tile
static constexpr int NTILE    = N_VEC / VTILE;    // 1024

// smem layout (floats)
static constexpr int OFF_T  = 0;                  // sT  [64][512]
static constexpr int OFF_E  = 32768;              // sE  [512]
static constexpr int OFF_X  = 33280;              // sX  [64][128]
static constexpr int OFF_S  = 41472;              // sS  [128]
static constexpr int OFF_B  = 41600;              // sB  [128]
static constexpr int OFF_CD = 41728;              // sCd [128][16]
static constexpr int OFF_CI = 43776;              // sCi [128][16]
static constexpr int SMEM_FLOATS = 45824;
static constexpr int SMEM_BYTES  = SMEM_FLOATS * 4;   // 183296

__device__ double   g_loss = 0.0;
__device__ unsigned g_done = 0u;

// R9 structure with LOW-PRESSURE mainloop: tk's 32 codes in 4 passes of 8
// (16 ull accs = 32 regs) so ptxas has ~35 free regs to pipeline LDS itself.
// Per d-iter: 1 x-LDS.128 (dense, tv=lane) + 2 e-LDS.128 (broadcast) + 4 movs + 16 fma2.
// EXACT-INVARIANT (verified rel_err==0.0 nine times, do not change):
//   d_k  = fl32( fl32(S + E_k) + (-2)*dot_k )
//   dot_k = strict sequential fp32 FMA chain over d=0..63
//   S     = 4-lane stride-4 sums combined (l0+l2)+(l1+l3)
//   argmin: strict '<', first-min ascending k (lane0<lane1; asc c; asc pass; asc tk)
//   out   = fl(x + fl(q - x))
__global__ __launch_bounds__(THREADS, 1)
void k_main(const float* __restrict__ in, const float* __restrict__ emb,
            float* __restrict__ out, int write_extras) {
    extern __shared__ float s[];
    float* sT  = s + OFF_T;
    float* sE  = s + OFF_E;
    float* sX  = s + OFF_X;
    float* sS  = s + OFF_S;
    int*   sB  = (int*)(s + OFF_B);
    float* sCd = s + OFF_CD;
    int*   sCi = (int*)(s + OFF_CI);
    __shared__ double red[16];

    const int tid = threadIdx.x;
    const int tv  = tid & 31;    // 4 vecs [tv*4, tv*4+3] (tv == lane -> dense x loads)
    const int tk  = tid >> 5;    // 32 codes [tk*32, tk*32+31] (uniform per warp -> broadcast e)

    // ---- stage codebook TRANSPOSED ----
#pragma unroll
    for (int i = 0; i < 64; i++) {
        int lin = i * THREADS + tid;
        int k = lin & 511;
        int d = lin >> 9;
        sT[d * K + k] = emb[k * D + d];
    }

    // ---- E_k: XLA 4-lane pattern, 1 code/thread ----
    {
        const float* r = emb + tid * D;
        float l0 = 0.f, l1 = 0.f, l2 = 0.f, l3 = 0.f;
#pragma unroll
        for (int i = 0; i < 16; i++) {
            l0 = __fadd_rn(l0, __fmul_rn(r[4 * i + 0], r[4 * i + 0]));
            l1 = __fadd_rn(l1, __fmul_rn(r[4 * i + 1], r[4 * i + 1]));
            l2 = __fadd_rn(l2, __fmul_rn(r[4 * i + 2], r[4 * i + 2]));
            l3 = __fadd_rn(l3, __fmul_rn(r[4 * i + 3], r[4 * i + 3]));
        }
        sE[tid] = __fadd_rn(__fadd_rn(l0, l2), __fadd_rn(l1, l3));
    }
    __syncthreads();

    const ull NEG2 = dup2(-2.0f);
    float lsumf = 0.0f;

    for (int tile = blockIdx.x; tile < NTILE; tile += NCTA) {
        const int v0 = tile * VTILE;
        const int b  = v0 >> 12;
        const int p  = v0 & 4095;
        const float* xg = in + b * (D * HW) + p;

        // ---- stage x tile [d][128] (coalesced) ----
#pragma unroll
        for (int i = 0; i < 16; i++) {
            int lin = i * THREADS + tid;
            int d   = lin >> 7;
            int vv2 = lin & 127;
            sX[lin] = xg[d * HW + vv2];
        }
        __syncthreads();

        // ---- S per vector (threads 0..127), exact 4-lane pattern ----
        if (tid < VTILE) {
            float l0 = 0.f, l1 = 0.f, l2 = 0.f, l3 = 0.f;
#pragma unroll
            for (int d = 0; d < 64; d += 4) {
                float x0 = sX[(d + 0) * VTILE + tid];
                float x1 = sX[(d + 1) * VTILE + tid];
                float x2 = sX[(d + 2) * VTILE + tid];
                float x3 = sX[(d + 3) * VTILE + tid];
                l0 = __fadd_rn(l0, __fmul_rn(x0, x0));
                l1 = __fadd_rn(l1, __fmul_rn(x1, x1));
                l2 = __fadd_rn(l2, __fmul_rn(x2, x2));
                l3 = __fadd_rn(l3, __fmul_rn(x3, x3));
            }
            sS[tid] = __fadd_rn(__fadd_rn(l0, l2), __fadd_rn(l1, l3));
        }
        __syncthreads();

        // ---- per-vec running best across 4 k-passes ----
        float bestD[4];
        int   bestI[4];
#pragma unroll
        for (int vp = 0; vp < 4; vp++) { bestD[vp] = 3.4e38f; bestI[vp] = 0; }

        const float4 Sv = *(const float4*)(sS + tv * 4);
        const ull Sd[4] = { dup2(Sv.x), dup2(Sv.y), dup2(Sv.z), dup2(Sv.w) };

#pragma unroll
        for (int pass = 0; pass < 4; pass++) {
            const int kb = tk * 32 + pass * 8;
            ull acc[16];
#pragma unroll
            for (int i = 0; i < 16; i++) acc[i] = 0ull;

            const float* xp = sX + tv * 4;
            const float* ep = sT + kb;

#pragma unroll 4
            for (int d = 0; d < 64; d++) {
                float4 xv = *(const float4*)(xp + d * VTILE);          // dense LDS.128
                const ulonglong2* eq = (const ulonglong2*)(ep + d * K); // broadcast
                ulonglong2 e01 = eq[0], e23 = eq[1];                   // 4 code-pairs
                ull x0 = dup2a(xv.x);
                ull x1 = dup2a(xv.y);
                ull x2 = dup2a(xv.z);
                ull x3 = dup2a(xv.w);
                ull ev[4] = { e01.x, e01.y, e23.x, e23.y };
#pragma unroll
                for (int c = 0; c < 4; c++) {
                    acc[0 * 4 + c] = fma2(x0, ev[c], acc[0 * 4 + c]);
                    acc[1 * 4 + c] = fma2(x1, ev[c], acc[1 * 4 + c]);
                    acc[2 * 4 + c] = fma2(x2, ev[c], acc[2 * 4 + c]);
                    acc[3 * 4 + c] = fma2(x3, ev[c], acc[3 * 4 + c]);
                }
            }

            // epilogue: distances + running argmin (ascending k)
            const ull* epE = (const ull*)(sE + kb);    // 4 E-pairs
#pragma unroll
            for (int c = 0; c < 4; c++) {
                ull Ec = epE[c];
                const int k0 = kb + 2 * c;
#pragma unroll
                for (int vp = 0; vp < 4; vp++) {
                    ull t1 = add2(Sd[vp], Ec);                 // fl(S + E)
                    ull dd = fma2(acc[vp * 4 + c], NEG2, t1);  // fl(t1 - 2*dot)
                    float d0 = ulo(dd), d1 = uhi(dd);
                    if (d0 < bestD[vp]) { bestD[vp] = d0; bestI[vp] = k0; }
                    if (d1 < bestD[vp]) { bestD[vp] = d1; bestI[vp] = k0 + 1; }
                }
            }
        }

        // ---- publish candidates [vec][tk] ----
#pragma unroll
        for (int vp = 0; vp < 4; vp++) {
            const int vvp = tv * 4 + vp;
            sCd[vvp * 16 + tk] = bestD[vp];
            sCi[vvp * 16 + tk] = bestI[vp];
        }
        __syncthreads();

        // ---- final reduce per vec (ascending tk = ascending k) ----
        if (tid < VTILE) {
            float best = 3.4e38f;
            int bi = 0;
#pragma unroll
            for (int t2 = 0; t2 < 16; t2++) {
                float dd = sCd[tid * 16 + t2];
                if (dd < best) { best = dd; bi = sCi[tid * 16 + t2]; }
            }
            sB[tid] = bi;
            if (write_extras) out[IDX_OFF + v0 + tid] = (float)bi;
        }
        __syncthreads();

        // ---- gather + straight-through store + loss (fp32): 16 elems/thread ----
        {
            const int vv2 = tid & 127;
            const int d0  = (tid >> 7) * 16;
            const int bi  = sB[vv2];
            float* og = out + b * (D * HW) + p + vv2;
#pragma unroll
            for (int j = 0; j < 16; j++) {
                const int d = d0 + j;
                float q  = sT[d * K + bi];
                float xs = sX[d * VTILE + vv2];
                float t  = __fsub_rn(q, xs);       // fl(q - x)
                og[d * HW] = __fadd_rn(xs, t);     // fl(x + (q - x))
                lsumf = __fmaf_rn(t, t, lsumf);
            }
        }
        __syncthreads();   // protect sX/sCd/sB before next tile
    }

    // ---- loss block-reduce (fp32 shfl, double combine) -> one atomic/CTA ----
#pragma unroll
    for (int o = 16; o; o >>= 1) lsumf += __shfl_down_sync(0xffffffffu, lsumf, o);
    if ((tid & 31) == 0) red[tid >> 5] = (double)lsumf;
    __syncthreads();
    if (tid == 0) {
        double t = 0.0;
#pragma unroll
        for (int w = 0; w < 16; w++) t += red[w];
        atomicAdd(&g_loss, t);
        __threadfence();
        unsigned done = atomicAdd(&g_done, 1u);
        if (done == (unsigned)(gridDim.x - 1)) {
            if (write_extras)
                out[LOSS_OFF] = (float)(0.25 * g_loss / (double)N_ELEMS);
            g_loss = 0.0;
            g_done = 0u;
        }
    }
}

extern "C" void kernel_launch(void* const* d_in, const int* in_sizes, int n_in,
                              void* d_out, int out_size) {
    const float* in  = (const float*)d_in[0];
    const float* emb = (const float*)d_in[1];
    if (n_in >= 2 && in_sizes[0] == K * D && in_sizes[1] == N_ELEMS) {
        const float* t = in; in = emb; emb = t;
    }
    float* out = (float*)d_out;

    cudaFuncSetAttribute(k_main, cudaFuncAttributeMaxDynamicSharedMemorySize, SMEM_BYTES);

    const int extras = (out_size > N_ELEMS) ? 1 : 0;

    k_main<<<NCTA, THREADS, SMEM_BYTES>>>(in, emb, out, extras);
}

// round 14
// speedup vs baseline: 1.3326x; 1.0507x over previous
#include <cuda_runtime.h>
#include <cstdint>

typedef unsigned long long ull;

// ---- packed f32x2 helpers: per-lane IEEE fp32 semantics ----
__device__ __forceinline__ ull fma2(ull a, ull b, ull c) {
    ull d;
    asm("fma.rn.f32x2 %0, %1, %2, %3;" : "=l"(d) : "l"(a), "l"(b), "l"(c));
    return d;
}
__device__ __forceinline__ ull add2(ull a, ull b) {
    ull d;
    asm("add.rn.f32x2 %0, %1, %2;" : "=l"(d) : "l"(a), "l"(b));
    return d;
}
__device__ __forceinline__ float ulo(ull v) { return __uint_as_float((unsigned)v); }
__device__ __forceinline__ float uhi(ull v) { return __uint_as_float((unsigned)(v >> 32)); }
__device__ __forceinline__ ull dup2a(float x) {
    ull d;
    asm("mov.b64 %0, {%1, %1};" : "=l"(d) : "f"(x));
    return d;
}
__device__ __forceinline__ ull dup2(float x) {
    unsigned u = __float_as_uint(x);
    return ((ull)u << 32) | (ull)u;
}

static constexpr int D       = 64;
static constexpr int HW      = 4096;
static constexpr int K       = 512;
static constexpr int N_VEC   = 131072;
static constexpr int N_ELEMS = N_VEC * D;         // 8388608
static constexpr int LOSS_OFF = N_ELEMS;
static constexpr int IDX_OFF  = N_ELEMS + 1;
static constexpr int THREADS  = 512;
static constexpr int NCTA     = 148;
static constexpr int VTILE    = 128;              // vectors per CTA-tile
static constexpr int NTILE    = N_VEC / VTILE;    // 1024

// smem layout (floats)
static constexpr int OFF_T  = 0;                  // sT  [64][512]
static constexpr int OFF_E  = 32768;              // sE  [512]
static constexpr int OFF_X  = 33280;              // sX  [64][128]
static constexpr int OFF_S  = 41472;              // sS  [128]
static constexpr int OFF_B  = 41600;              // sB  [128]
static constexpr int OFF_CD = 41728;              // sCd [128][8]
static constexpr int OFF_CI = 42752;              // sCi [128][8]
static constexpr int SMEM_FLOATS = 43776;
static constexpr int SMEM_BYTES  = SMEM_FLOATS * 4;   // 175104

__device__ double   g_loss = 0.0;
__device__ unsigned g_done = 0u;

// R13 structure, retuned thread tile: 2 vectors x 64 codes in 4 passes of 16
// (16 ull accs = 32 regs). Same smem traffic per fma2 as R9 (x: LDS.64 dense,
// e: 2x LDS.128 broadcast per d-iter) but ~45 free regs -> ptxas pipelines LDS.
// EXACT-INVARIANT (verified rel_err==0.0 ten times, do not change):
//   d_k  = fl32( fl32(S + E_k) + (-2)*dot_k )
//   dot_k = strict sequential fp32 FMA chain over d=0..63
//   S     = 4-lane stride-4 sums combined (l0+l2)+(l1+l3)
//   argmin: strict '<', first-min ascending k (lane0<lane1; asc c; asc pass; asc tk)
//   out   = fl(x + fl(q - x))
__global__ __launch_bounds__(THREADS, 1)
void k_main(const float* __restrict__ in, const float* __restrict__ emb,
            float* __restrict__ out, int write_extras) {
    extern __shared__ float s[];
    float* sT  = s + OFF_T;
    float* sE  = s + OFF_E;
    float* sX  = s + OFF_X;
    float* sS  = s + OFF_S;
    int*   sB  = (int*)(s + OFF_B);
    float* sCd = s + OFF_CD;
    int*   sCi = (int*)(s + OFF_CI);
    __shared__ double red[16];

    const int tid = threadIdx.x;
    const int tv  = tid & 63;    // 2 vecs [tv*2, tv*2+1] (dense LDS.64 x-loads)
    const int tk  = tid >> 6;    // 0..7: 64 codes [tk*64, tk*64+63] (uniform per warp)

    // ---- stage codebook TRANSPOSED ----
#pragma unroll
    for (int i = 0; i < 64; i++) {
        int lin = i * THREADS + tid;
        int k = lin & 511;
        int d = lin >> 9;
        sT[d * K + k] = emb[k * D + d];
    }

    // ---- E_k: XLA 4-lane pattern, 1 code/thread ----
    {
        const float* r = emb + tid * D;
        float l0 = 0.f, l1 = 0.f, l2 = 0.f, l3 = 0.f;
#pragma unroll
        for (int i = 0; i < 16; i++) {
            l0 = __fadd_rn(l0, __fmul_rn(r[4 * i + 0], r[4 * i + 0]));
            l1 = __fadd_rn(l1, __fmul_rn(r[4 * i + 1], r[4 * i + 1]));
            l2 = __fadd_rn(l2, __fmul_rn(r[4 * i + 2], r[4 * i + 2]));
            l3 = __fadd_rn(l3, __fmul_rn(r[4 * i + 3], r[4 * i + 3]));
        }
        sE[tid] = __fadd_rn(__fadd_rn(l0, l2), __fadd_rn(l1, l3));
    }
    __syncthreads();

    const ull NEG2 = dup2(-2.0f);
    float lsumf = 0.0f;

    for (int tile = blockIdx.x; tile < NTILE; tile += NCTA) {
        const int v0 = tile * VTILE;
        const int b  = v0 >> 12;
        const int p  = v0 & 4095;
        const float* xg = in + b * (D * HW) + p;

        // ---- stage x tile [d][128] (coalesced) ----
#pragma unroll
        for (int i = 0; i < 16; i++) {
            int lin = i * THREADS + tid;
            int d   = lin >> 7;
            int vv2 = lin & 127;
            sX[lin] = xg[d * HW + vv2];
        }
        __syncthreads();

        // ---- S per vector (threads 0..127), exact 4-lane pattern ----
        if (tid < VTILE) {
            float l0 = 0.f, l1 = 0.f, l2 = 0.f, l3 = 0.f;
#pragma unroll
            for (int d = 0; d < 64; d += 4) {
                float x0 = sX[(d + 0) * VTILE + tid];
                float x1 = sX[(d + 1) * VTILE + tid];
                float x2 = sX[(d + 2) * VTILE + tid];
                float x3 = sX[(d + 3) * VTILE + tid];
                l0 = __fadd_rn(l0, __fmul_rn(x0, x0));
                l1 = __fadd_rn(l1, __fmul_rn(x1, x1));
                l2 = __fadd_rn(l2, __fmul_rn(x2, x2));
                l3 = __fadd_rn(l3, __fmul_rn(x3, x3));
            }
            sS[tid] = __fadd_rn(__fadd_rn(l0, l2), __fadd_rn(l1, l3));
        }
        __syncthreads();

        // ---- per-vec running best across 4 k-passes ----
        float bestD[2];
        int   bestI[2];
#pragma unroll
        for (int vp = 0; vp < 2; vp++) { bestD[vp] = 3.4e38f; bestI[vp] = 0; }

        const float2 Sv = *(const float2*)(sS + tv * 2);
        const ull Sd[2] = { dup2(Sv.x), dup2(Sv.y) };

#pragma unroll
        for (int pass = 0; pass < 4; pass++) {
            const int kb = tk * 64 + pass * 16;
            ull acc[16];
#pragma unroll
            for (int i = 0; i < 16; i++) acc[i] = 0ull;

            const float* xp = sX + tv * 2;
            const float* ep = sT + kb;

#pragma unroll 4
            for (int d = 0; d < 64; d++) {
                float2 xv = *(const float2*)(xp + d * VTILE);           // dense LDS.64
                const ulonglong2* eq = (const ulonglong2*)(ep + d * K); // broadcast
                ulonglong2 e01 = eq[0], e23 = eq[1], e45 = eq[2], e67 = eq[3]; // 8 pairs
                ull x0 = dup2a(xv.x);
                ull x1 = dup2a(xv.y);
                ull ev[8] = { e01.x, e01.y, e23.x, e23.y, e45.x, e45.y, e67.x, e67.y };
#pragma unroll
                for (int c = 0; c < 8; c++) {
                    acc[0 * 8 + c] = fma2(x0, ev[c], acc[0 * 8 + c]);
                    acc[1 * 8 + c] = fma2(x1, ev[c], acc[1 * 8 + c]);
                }
            }

            // epilogue: distances + running argmin (ascending k)
            const ull* epE = (const ull*)(sE + kb);    // 8 E-pairs
#pragma unroll
            for (int c = 0; c < 8; c++) {
                ull Ec = epE[c];
                const int k0 = kb + 2 * c;
#pragma unroll
                for (int vp = 0; vp < 2; vp++) {
                    ull t1 = add2(Sd[vp], Ec);                 // fl(S + E)
                    ull dd = fma2(acc[vp * 8 + c], NEG2, t1);  // fl(t1 - 2*dot)
                    float d0 = ulo(dd), d1 = uhi(dd);
                    if (d0 < bestD[vp]) { bestD[vp] = d0; bestI[vp] = k0; }
                    if (d1 < bestD[vp]) { bestD[vp] = d1; bestI[vp] = k0 + 1; }
                }
            }
        }

        // ---- publish candidates [vec][tk] ----
#pragma unroll
        for (int vp = 0; vp < 2; vp++) {
            const int vvp = tv * 2 + vp;
            sCd[vvp * 8 + tk] = bestD[vp];
            sCi[vvp * 8 + tk] = bestI[vp];
        }
        __syncthreads();

        // ---- final reduce per vec (ascending tk = ascending k) ----
        if (tid < VTILE) {
            float best = 3.4e38f;
            int bi = 0;
#pragma unroll
            for (int t2 = 0; t2 < 8; t2++) {
                float dd = sCd[tid * 8 + t2];
                if (dd < best) { best = dd; bi = sCi[tid * 8 + t2]; }
            }
            sB[tid] = bi;
            if (write_extras) out[IDX_OFF + v0 + tid] = (float)bi;
        }
        __syncthreads();

        // ---- gather + straight-through store + loss (fp32): 16 elems/thread ----
        {
            const int vv2 = tid & 127;
            const int d0  = (tid >> 7) * 16;
            const int bi  = sB[vv2];
            float* og = out + b * (D * HW) + p + vv2;
#pragma unroll
            for (int j = 0; j < 16; j++) {
                const int d = d0 + j;
                float q  = sT[d * K + bi];
                float xs = sX[d * VTILE + vv2];
                float t  = __fsub_rn(q, xs);       // fl(q - x)
                og[d * HW] = __fadd_rn(xs, t);     // fl(x + (q - x))
                lsumf = __fmaf_rn(t, t, lsumf);
            }
        }
        __syncthreads();   // protect sX/sCd/sB before next tile
    }

    // ---- loss block-reduce (fp32 shfl, double combine) -> one atomic/CTA ----
#pragma unroll
    for (int o = 16; o; o >>= 1) lsumf += __shfl_down_sync(0xffffffffu, lsumf, o);
    if ((tid & 31) == 0) red[tid >> 5] = (double)lsumf;
    __syncthreads();
    if (tid == 0) {
        double t = 0.0;
#pragma unroll
        for (int w = 0; w < 16; w++) t += red[w];
        atomicAdd(&g_loss, t);
        __threadfence();
        unsigned done = atomicAdd(&g_done, 1u);
        if (done == (unsigned)(gridDim.x - 1)) {
            if (write_extras)
                out[LOSS_OFF] = (float)(0.25 * g_loss / (double)N_ELEMS);
            g_loss = 0.0;
            g_done = 0u;
        }
    }
}

extern "C" void kernel_launch(void* const* d_in, const int* in_sizes, int n_in,
                              void* d_out, int out_size) {
    const float* in  = (const float*)d_in[0];
    const float* emb = (const float*)d_in[1];
    if (n_in >= 2 && in_sizes[0] == K * D && in_sizes[1] == N_ELEMS) {
        const float* t = in; in = emb; emb = t;
    }
    float* out = (float*)d_out;

    cudaFuncSetAttribute(k_main, cudaFuncAttributeMaxDynamicSharedMemorySize, SMEM_BYTES);

    const int extras = (out_size > N_ELEMS) ? 1 : 0;

    k_main<<<NCTA, THREADS, SMEM_BYTES>>>(in, emb, out, extras);
}